// round 2
// baseline (speedup 1.0000x reference)
#include <cuda_runtime.h>

#define T_STEPS 512
#define BATCH   2048
#define IN_DIM  12
#define E_DIM   15
#define H_DIM   20
#define ROWS_PB 7
#define NTHREADS (ROWS_PB * H_DIM * 4)              // 560
#define NGRID   ((BATCH + ROWS_PB - 1) / ROWS_PB)   // 293  (all co-resident, 2/SM)

// ---- packed f32x2 helpers (Blackwell sm_103a) ----
__device__ __forceinline__ unsigned long long pack2(float x, float y) {
    unsigned long long u;
    asm("mov.b64 %0, {%1, %2};" : "=l"(u) : "f"(x), "f"(y));
    return u;
}
__device__ __forceinline__ void fma2(unsigned long long& d,
                                     unsigned long long a,
                                     unsigned long long b) {
    asm("fma.rn.f32x2 %0, %1, %2, %0;" : "+l"(d) : "l"(a), "l"(b));
}
__device__ __forceinline__ float hsum2(unsigned long long u) {
    float x, y;
    asm("mov.b64 {%0, %1}, %2;" : "=f"(x), "=f"(y) : "l"(u));
    return x + y;
}
__device__ __forceinline__ float tanh_a(float x) {
    float y;
    asm("tanh.approx.f32 %0, %1;" : "=f"(y) : "f"(x));   // 1 MUFU op
    return y;
}

__global__ void __launch_bounds__(NTHREADS, 2)
lstm_tracker_kernel(const float* __restrict__ X,
                    const float* __restrict__ Wemb, const float* __restrict__ bemb,
                    const float* __restrict__ Wih,  const float* __restrict__ bih,
                    const float* __restrict__ Whh,  const float* __restrict__ bhh,
                    const float* __restrict__ Wout, const float* __restrict__ bout,
                    float* __restrict__ out)
{
    __shared__ __align__(16) float s_wemb[E_DIM * IN_DIM];   // 180
    __shared__ __align__(16) float s_wih[4 * H_DIM * E_DIM]; // 1200
    __shared__ __align__(16) float s_wout[3 * H_DIM];        // 60
    __shared__ float s_bout[3];
    __shared__ float s_bemb[E_DIM];
    __shared__ __align__(16) float x_s[2][ROWS_PB][IN_DIM];  // ping-pong x[t]
    __shared__ __align__(16) float h_s[2][ROWS_PB][H_DIM];   // ping-pong h

    const int tid  = threadIdx.x;
    const int g    = tid & 3;                 // gate index (i,f,g,o)
    const int k    = (tid % (H_DIM * 4)) >> 2;// hidden unit 0..19
    const int row  = tid / (H_DIM * 4);       // local batch row 0..6
    const int grow = blockIdx.x * ROWS_PB + row;
    const bool valid = grow < BATCH;

    // ---- cooperative weight staging ----
    for (int i = tid; i < E_DIM * IN_DIM; i += NTHREADS)     s_wemb[i] = Wemb[i];
    for (int i = tid; i < 4 * H_DIM * E_DIM; i += NTHREADS)  s_wih[i]  = Wih[i];
    if (tid < 3 * H_DIM) s_wout[tid] = Wout[tid];
    if (tid < 3)         s_bout[tid] = bout[tid];
    if (tid < E_DIM)     s_bemb[tid] = bemb[tid];
    for (int i = tid; i < 2 * ROWS_PB * H_DIM; i += NTHREADS)
        (&h_s[0][0][0])[i] = 0.0f;
    for (int i = tid; i < 2 * ROWS_PB * IN_DIM; i += NTHREADS)
        (&x_s[0][0][0])[i] = 0.0f;
    __syncthreads();

    // ---- per-thread register weights for gate r = g*H + k ----
    // Fused input weights: Wc[r][j] = sum_e Wih[r][e] * Wemb[e][j]
    // Fused bias:          bc       = bih[r] + bhh[r] + sum_e Wih[r][e]*bemb[e]
    const int r = g * H_DIM + k;
    float bc = bih[r] + bhh[r];
#pragma unroll
    for (int e = 0; e < E_DIM; ++e) bc += s_wih[r * E_DIM + e] * s_bemb[e];

    unsigned long long wc[IN_DIM / 2];   // 6 x u64
    unsigned long long wh[H_DIM / 2];    // 10 x u64
#pragma unroll
    for (int jj = 0; jj < IN_DIM / 2; ++jj) {
        float c0 = 0.0f, c1 = 0.0f;
#pragma unroll
        for (int e = 0; e < E_DIM; ++e) {
            const float wie = s_wih[r * E_DIM + e];
            c0 += wie * s_wemb[e * IN_DIM + 2 * jj];
            c1 += wie * s_wemb[e * IN_DIM + 2 * jj + 1];
        }
        wc[jj] = pack2(c0, c1);
    }
#pragma unroll
    for (int jj = 0; jj < H_DIM / 2; ++jj)
        wh[jj] = pack2(Whh[r * H_DIM + 2 * jj], Whh[r * H_DIM + 2 * jj + 1]);

    // ---- preload x[0] ----
    {
        const int xbase = blockIdx.x * (ROWS_PB * IN_DIM);
        if (tid < ROWS_PB * IN_DIM && xbase + tid < BATCH * IN_DIM)
            (&x_s[0][0][0])[tid] = X[xbase + tid];
    }
    float c = 0.0f;
    __syncthreads();

    const long long xstride = (long long)BATCH * IN_DIM;
    int buf = 0;

    for (int t = 0; t < T_STEPS; ++t) {
        // prefetch x[t+1] early (latency hidden under gate math)
        const int xbase = blockIdx.x * (ROWS_PB * IN_DIM);
        const bool pre = (tid < ROWS_PB * IN_DIM) && (t + 1 < T_STEPS) &&
                         (xbase + tid < BATCH * IN_DIM);
        float xpre = 0.0f;
        if (pre) xpre = X[(long long)(t + 1) * xstride + xbase + tid];

        // ---- this thread's single-gate dot product, two accumulators for ILP ----
        unsigned long long accx = pack2(bc, 0.0f);
        unsigned long long acch = pack2(0.0f, 0.0f);

        const float4* xr4 = reinterpret_cast<const float4*>(x_s[buf][row]);
        {
            const float4 xa = xr4[0], xb = xr4[1], xc4 = xr4[2];
            fma2(accx, wc[0], pack2(xa.x, xa.y));
            fma2(accx, wc[1], pack2(xa.z, xa.w));
            fma2(accx, wc[2], pack2(xb.x, xb.y));
            fma2(accx, wc[3], pack2(xb.z, xb.w));
            fma2(accx, wc[4], pack2(xc4.x, xc4.y));
            fma2(accx, wc[5], pack2(xc4.z, xc4.w));
        }
        const float4* hr4 = reinterpret_cast<const float4*>(h_s[buf][row]);
#pragma unroll
        for (int q = 0; q < 5; ++q) {
            const float4 hv = hr4[q];
            fma2(acch, wh[2 * q],     pack2(hv.x, hv.y));
            fma2(acch, wh[2 * q + 1], pack2(hv.z, hv.w));
        }

        const float pre_act = hsum2(accx) + hsum2(acch);
        // gates i,f,o: sigmoid via tanh; gate g (g==2): tanh
        const float th  = (g == 2) ? tanh_a(pre_act)
                                   : fmaf(0.5f, tanh_a(0.5f * pre_act), 0.5f);

        // gather the 4 gate activations within the aligned 4-lane group
        const unsigned mask = 0xffffffffu;
        const float iv = __shfl_sync(mask, th, 0, 4);
        const float fv = __shfl_sync(mask, th, 1, 4);
        const float gv = __shfl_sync(mask, th, 2, 4);
        const float ov = __shfl_sync(mask, th, 3, 4);

        c = fv * c + iv * gv;                 // identical in all 4 lanes
        const float hk = ov * tanh_a(c);
        if (g == 0) h_s[buf ^ 1][row][k] = hk;

        // output projection for step t-1 (reads stable h_s[buf] = h_{t-1})
        if (g == 1 && k < 3 && t > 0 && valid) {
            float acc = s_bout[k];
            const float4* hp = reinterpret_cast<const float4*>(h_s[buf][row]);
#pragma unroll
            for (int q = 0; q < 5; ++q) {
                const float4 hv = hp[q];
                acc += s_wout[k * H_DIM + 4 * q]     * hv.x;
                acc += s_wout[k * H_DIM + 4 * q + 1] * hv.y;
                acc += s_wout[k * H_DIM + 4 * q + 2] * hv.z;
                acc += s_wout[k * H_DIM + 4 * q + 3] * hv.w;
            }
            out[(long long)(t - 1) * (BATCH * 3) + grow * 3 + k] = acc;
        }

        if (pre) (&x_s[buf ^ 1][0][0])[tid] = xpre;

        __syncthreads();
        buf ^= 1;
    }

    // final output for t = T-1
    if (g == 1 && k < 3 && valid) {
        float acc = s_bout[k];
        const float4* hp = reinterpret_cast<const float4*>(h_s[buf][row]);
#pragma unroll
        for (int q = 0; q < 5; ++q) {
            const float4 hv = hp[q];
            acc += s_wout[k * H_DIM + 4 * q]     * hv.x;
            acc += s_wout[k * H_DIM + 4 * q + 1] * hv.y;
            acc += s_wout[k * H_DIM + 4 * q + 2] * hv.z;
            acc += s_wout[k * H_DIM + 4 * q + 3] * hv.w;
        }
        out[(long long)(T_STEPS - 1) * (BATCH * 3) + grow * 3 + k] = acc;
    }
}

extern "C" void kernel_launch(void* const* d_in, const int* in_sizes, int n_in,
                              void* d_out, int out_size) {
    const float* X    = (const float*)d_in[0];
    const float* Wemb = (const float*)d_in[1];
    const float* bemb = (const float*)d_in[2];
    const float* Wih  = (const float*)d_in[3];
    const float* bih  = (const float*)d_in[4];
    const float* Whh  = (const float*)d_in[5];
    const float* bhh  = (const float*)d_in[6];
    const float* Wout = (const float*)d_in[7];
    const float* bout = (const float*)d_in[8];
    float* out = (float*)d_out;

    lstm_tracker_kernel<<<NGRID, NTHREADS>>>(X, Wemb, bemb, Wih, bih,
                                             Whh, bhh, Wout, bout, out);
}